// round 6
// baseline (speedup 1.0000x reference)
#include <cuda_runtime.h>
#include <cuda_bf16.h>
#include <cstdint>

// Problem constants (fixed by the dataset)
#define NN   4096
#define FDIM 256
#define BB   8
#define MTOT (BB * NN)          // 32768 rows
#define WPR  (NN / 32)
#define MAXD 128

// -------- scratch (static __device__ arrays; no allocation allowed) --------
__device__ unsigned g_adj[NN * WPR];
__device__ int      g_deg[NN];
__device__ int      g_nbr[NN * MAXD];
__device__ __align__(16) float         g_xt[(size_t)MTOT * FDIM];   // 32 MB
__device__ __align__(16) __nv_bfloat16 g_wh[FDIM * FDIM];           // W^T hi [n][k]
__device__ __align__(16) __nv_bfloat16 g_wl[FDIM * FDIM];           // W^T lo [n][k]

// ---------------------------------------------------------------------------
// Kernel 1: zero bitmask + degree
// ---------------------------------------------------------------------------
__global__ void k_zero() {
    int i = blockIdx.x * blockDim.x + threadIdx.x;
    if (i < NN * WPR) g_adj[i] = 0u;
    if (i < NN)       g_deg[i] = 0;
}

// ---------------------------------------------------------------------------
// Kernel 2: build dedup'd neighbor lists
// ---------------------------------------------------------------------------
__global__ void k_edges(const int* __restrict__ ei, int E) {
    int e = blockIdx.x * blockDim.x + threadIdx.x;
    if (e >= E) return;
    int src = ei[e];
    int dst = ei[E + e];
    unsigned mask = 1u << (dst & 31);
    unsigned old = atomicOr(&g_adj[src * WPR + (dst >> 5)], mask);
    if (!(old & mask)) {
        int pos = atomicAdd(&g_deg[src], 1);
        if (pos < MAXD) g_nbr[src * MAXD + pos] = dst;
    }
}

// ---------------------------------------------------------------------------
// Kernel 3: weight prep — transpose + bf16 hi/lo split
// ---------------------------------------------------------------------------
__global__ void k_wprep(const float* __restrict__ w) {
    int i = blockIdx.x * blockDim.x + threadIdx.x;
    if (i >= FDIM * FDIM) return;
    int k = i >> 8, n = i & 255;
    float v = w[i];
    __nv_bfloat16 h = __float2bfloat16(v);
    __nv_bfloat16 l = __float2bfloat16(v - __bfloat162float(h));
    g_wh[n * FDIM + k] = h;
    g_wl[n * FDIM + k] = l;
}

// ---------------------------------------------------------------------------
// Kernel 4: xt = x @ W via bf16 mma.sync, 3-term split.
// A fragments loaded DIRECTLY from global into registers (fragment layout
// matches row-major float2 loads) + in-register fp32->bf16 hi/lo conversion.
// B (hi+lo, full K=256) resident in smem. NO barriers in the k-loop.
// ---------------------------------------------------------------------------
#define BSTR  264                // B smem row stride in halves (256 + 8 pad)
#define SB_H  0                  // 64 * 264 * 2 = 33792 bytes per plane
#define SB_L  33792
#define S_TOT 67584

extern __shared__ char dsm[];

__device__ __forceinline__ uint32_t smem_u32(const void* p) {
    uint32_t a;
    asm("{ .reg .u64 t; cvta.to.shared.u64 t, %1; cvt.u32.u64 %0, t; }"
        : "=r"(a) : "l"(p));
    return a;
}
__device__ __forceinline__ void ldsm_x2(uint32_t* r, uint32_t addr) {
    asm volatile("ldmatrix.sync.aligned.m8n8.x2.shared.b16 {%0,%1}, [%2];"
                 : "=r"(r[0]), "=r"(r[1]) : "r"(addr));
}
__device__ __forceinline__ void mma_bf16(float* c, const uint32_t* a,
                                         const uint32_t* b) {
    asm volatile(
        "mma.sync.aligned.m16n8k16.row.col.f32.bf16.bf16.f32 "
        "{%0,%1,%2,%3}, {%4,%5,%6,%7}, {%8,%9}, {%0,%1,%2,%3};"
        : "+f"(c[0]), "+f"(c[1]), "+f"(c[2]), "+f"(c[3])
        : "r"(a[0]), "r"(a[1]), "r"(a[2]), "r"(a[3]), "r"(b[0]), "r"(b[1]));
}
__device__ __forceinline__ uint32_t packbf2(float a, float b) {
    __nv_bfloat162 p = __floats2bfloat162_rn(a, b);
    return *(uint32_t*)&p;
}
// float2 -> packed bf16 hi + residual lo
__device__ __forceinline__ void cvt_hilo(float2 v, uint32_t& h, uint32_t& l) {
    __nv_bfloat16 h0 = __float2bfloat16(v.x);
    __nv_bfloat16 h1 = __float2bfloat16(v.y);
    h = (uint32_t)__bfloat16_as_ushort(h0) |
        ((uint32_t)__bfloat16_as_ushort(h1) << 16);
    l = packbf2(v.x - __bfloat162float(h0), v.y - __bfloat162float(h1));
}

__global__ void __launch_bounds__(256, 2)
k_gemm_tc(const float* __restrict__ x) {
    const int tid  = threadIdx.x;
    const int lane = tid & 31;
    const int w    = tid >> 5;
    const int wm   = w >> 1;          // 0..3 (32-row block)
    const int wn   = w & 1;           // 0..1 (32-col block)
    const int n0   = blockIdx.x * 64;
    const int m0   = blockIdx.y * 128;
    const uint32_t sb = smem_u32(dsm);

    // ---- preload B (hi + lo, 64 n x 256 k) into smem ----
    #pragma unroll
    for (int q = 0; q < 8; q++) {
        int idx = q * 256 + tid;          // 0..2047
        int n = idx >> 5;                 // 0..63
        int u = idx & 31;                 // uint4 within row
        *(uint4*)(dsm + SB_H + n * (BSTR * 2) + u * 16) =
            *(const uint4*)&g_wh[(size_t)(n0 + n) * FDIM + u * 8];
        *(uint4*)(dsm + SB_L + n * (BSTR * 2) + u * 16) =
            *(const uint4*)&g_wl[(size_t)(n0 + n) * FDIM + u * 8];
    }
    __syncthreads();

    // ---- A fragment base pointer (mma m16n8k16 layout == row-major float2) ----
    const float* ap = x + (size_t)(m0 + wm * 32 + (lane >> 2)) * FDIM +
                      ((lane & 3) << 1);
    const uint32_t brow = (uint32_t)(wn * 32 + (lane & 7)) * (BSTR * 2) +
                          (uint32_t)(((lane >> 3) & 1) * 8) * 2;

    float acc[2][4][4];
    #pragma unroll
    for (int i = 0; i < 2; i++)
        #pragma unroll
        for (int j = 0; j < 4; j++)
            #pragma unroll
            for (int r = 0; r < 4; r++) acc[i][j][r] = 0.f;

    // prologue: load A for k-step 0
    float2 pv[2][4];
    #pragma unroll
    for (int i = 0; i < 2; i++) {
        const float* p = ap + i * 16 * FDIM;
        pv[i][0] = *(const float2*)(p);
        pv[i][1] = *(const float2*)(p + 8 * FDIM);
        pv[i][2] = *(const float2*)(p + 8);
        pv[i][3] = *(const float2*)(p + 8 * FDIM + 8);
    }

    #pragma unroll
    for (int kk = 0; kk < 16; kk++) {
        // prefetch next A chunk
        float2 nv[2][4];
        if (kk + 1 < 16) {
            const int kn = (kk + 1) * 16;
            #pragma unroll
            for (int i = 0; i < 2; i++) {
                const float* p = ap + i * 16 * FDIM + kn;
                nv[i][0] = *(const float2*)(p);
                nv[i][1] = *(const float2*)(p + 8 * FDIM);
                nv[i][2] = *(const float2*)(p + 8);
                nv[i][3] = *(const float2*)(p + 8 * FDIM + 8);
            }
        }

        // convert current A to hi/lo fragments
        uint32_t aH[2][4], aL[2][4];
        #pragma unroll
        for (int i = 0; i < 2; i++)
            #pragma unroll
            for (int q = 0; q < 4; q++)
                cvt_hilo(pv[i][q], aH[i][q], aL[i][q]);

        // B fragments for this k16
        const uint32_t kb = (uint32_t)(kk * 16) * 2;
        uint32_t bH[4][2], bL[4][2];
        #pragma unroll
        for (int j = 0; j < 4; j++)
            ldsm_x2(bH[j], sb + SB_H + brow + kb + j * 8 * (BSTR * 2));
        #pragma unroll
        for (int j = 0; j < 4; j++)
            ldsm_x2(bL[j], sb + SB_L + brow + kb + j * 8 * (BSTR * 2));

        // 24 mma: Ah*Bh + Ah*Bl + Al*Bh
        #pragma unroll
        for (int i = 0; i < 2; i++)
            #pragma unroll
            for (int j = 0; j < 4; j++) mma_bf16(acc[i][j], aH[i], bH[j]);
        #pragma unroll
        for (int i = 0; i < 2; i++)
            #pragma unroll
            for (int j = 0; j < 4; j++) mma_bf16(acc[i][j], aH[i], bL[j]);
        #pragma unroll
        for (int i = 0; i < 2; i++)
            #pragma unroll
            for (int j = 0; j < 4; j++) mma_bf16(acc[i][j], aL[i], bH[j]);

        #pragma unroll
        for (int i = 0; i < 2; i++)
            #pragma unroll
            for (int q = 0; q < 4; q++) pv[i][q] = nv[i][q];
    }

    // ---- epilogue: D fragment -> g_xt ----
    #pragma unroll
    for (int i = 0; i < 2; i++) {
        #pragma unroll
        for (int j = 0; j < 4; j++) {
            int m = m0 + wm * 32 + i * 16 + (lane >> 2);
            int n = n0 + wn * 32 + j * 8 + (lane & 3) * 2;
            *(float2*)&g_xt[(size_t)m * FDIM + n] =
                make_float2(acc[i][j][0], acc[i][j][1]);
            *(float2*)&g_xt[(size_t)(m + 8) * FDIM + n] =
                make_float2(acc[i][j][2], acc[i][j][3]);
        }
    }
}

// ---------------------------------------------------------------------------
// Kernel 5: sparse aggregation. 2 sources per block; float2 feature lanes
// (halves LSU instruction count; L2 traffic unchanged).
// ---------------------------------------------------------------------------
__global__ void __launch_bounds__(256)
k_agg(const float* __restrict__ bias, float* __restrict__ out) {
    const int half = threadIdx.x >> 7;          // 0 or 1
    const int src  = blockIdx.x * 2 + half;
    const int t    = threadIdx.x & 127;         // 0..127
    const int f    = t << 1;                    // feature pair base

    __shared__ int snb[2][MAXD];
    int deg = g_deg[src];
    if (deg > MAXD) deg = MAXD;
    if (t < deg) snb[half][t] = g_nbr[src * MAXD + t];
    __syncthreads();

    const float inv = 1.0f / ((float)deg + 1e-6f);
    const float2 bf = *(const float2*)&bias[f];

    float2 acc[BB];
    #pragma unroll
    for (int b = 0; b < BB; b++) acc[b] = make_float2(0.f, 0.f);

    const size_t batch_stride = (size_t)NN * FDIM;

    int i = 0;
    for (; i + 2 <= deg; i += 2) {
        const float* p0 = &g_xt[(size_t)snb[half][i]     * FDIM + f];
        const float* p1 = &g_xt[(size_t)snb[half][i + 1] * FDIM + f];
        float2 v0[BB], v1[BB];
        #pragma unroll
        for (int b = 0; b < BB; b++) v0[b] = *(const float2*)(p0 + b * batch_stride);
        #pragma unroll
        for (int b = 0; b < BB; b++) v1[b] = *(const float2*)(p1 + b * batch_stride);
        #pragma unroll
        for (int b = 0; b < BB; b++) {
            acc[b].x += v0[b].x + v1[b].x;
            acc[b].y += v0[b].y + v1[b].y;
        }
    }
    if (i < deg) {
        const float* p0 = &g_xt[(size_t)snb[half][i] * FDIM + f];
        #pragma unroll
        for (int b = 0; b < BB; b++) {
            float2 v = *(const float2*)(p0 + b * batch_stride);
            acc[b].x += v.x;
            acc[b].y += v.y;
        }
    }

    #pragma unroll
    for (int b = 0; b < BB; b++)
        *(float2*)&out[((size_t)b * NN + src) * FDIM + f] =
            make_float2(acc[b].x * inv + bf.x, acc[b].y * inv + bf.y);
}

// ---------------------------------------------------------------------------
extern "C" void kernel_launch(void* const* d_in, const int* in_sizes, int n_in,
                              void* d_out, int out_size) {
    const float* x    = (const float*)d_in[0];   // (8, 4096, 256) f32
    const int*   ei   = (const int*)  d_in[1];   // (2, 131072) i32
    const float* w    = (const float*)d_in[2];   // (256, 256) f32
    const float* bias = (const float*)d_in[3];   // (256,) f32
    float* out = (float*)d_out;

    const int E = in_sizes[1] / 2;

    cudaFuncSetAttribute(k_gemm_tc, cudaFuncAttributeMaxDynamicSharedMemorySize,
                         S_TOT);

    k_zero<<<(NN * WPR + 255) / 256, 256>>>();
    k_edges<<<(E + 255) / 256, 256>>>(ei, E);
    k_wprep<<<(FDIM * FDIM + 255) / 256, 256>>>(w);
    k_gemm_tc<<<dim3(4, MTOT / 128), 256, S_TOT>>>(x);
    k_agg<<<NN / 2, 256>>>(bias, out);
}

// round 7
// speedup vs baseline: 1.1800x; 1.1800x over previous
#include <cuda_runtime.h>
#include <cuda_bf16.h>
#include <cuda_fp16.h>
#include <cstdint>

// Problem constants (fixed by the dataset)
#define NN   4096
#define FDIM 256
#define BB   8
#define MTOT (BB * NN)          // 32768 rows
#define WPR  (NN / 32)
#define MAXD 128

// -------- scratch (static __device__ arrays; no allocation allowed) --------
__device__ unsigned g_adj[NN * WPR];
__device__ int      g_deg[NN];
__device__ int      g_nbr[NN * MAXD];
__device__ __align__(16) __half        g_xth[(size_t)MTOT * FDIM];  // 16 MB fp16 xt
__device__ __align__(16) __nv_bfloat16 g_wh[FDIM * FDIM];           // W^T hi [n][k]
__device__ __align__(16) __nv_bfloat16 g_wl[FDIM * FDIM];           // W^T lo [n][k]

// ---------------------------------------------------------------------------
// Kernel 1: zero bitmask + degree
// ---------------------------------------------------------------------------
__global__ void k_zero() {
    int i = blockIdx.x * blockDim.x + threadIdx.x;
    if (i < NN * WPR) g_adj[i] = 0u;
    if (i < NN)       g_deg[i] = 0;
}

// ---------------------------------------------------------------------------
// Kernel 2: build dedup'd neighbor lists
// ---------------------------------------------------------------------------
__global__ void k_edges(const int* __restrict__ ei, int E) {
    int e = blockIdx.x * blockDim.x + threadIdx.x;
    if (e >= E) return;
    int src = ei[e];
    int dst = ei[E + e];
    unsigned mask = 1u << (dst & 31);
    unsigned old = atomicOr(&g_adj[src * WPR + (dst >> 5)], mask);
    if (!(old & mask)) {
        int pos = atomicAdd(&g_deg[src], 1);
        if (pos < MAXD) g_nbr[src * MAXD + pos] = dst;
    }
}

// ---------------------------------------------------------------------------
// Kernel 3: weight prep — transpose + bf16 hi/lo split
// ---------------------------------------------------------------------------
__global__ void k_wprep(const float* __restrict__ w) {
    int i = blockIdx.x * blockDim.x + threadIdx.x;
    if (i >= FDIM * FDIM) return;
    int k = i >> 8, n = i & 255;
    float v = w[i];
    __nv_bfloat16 h = __float2bfloat16(v);
    __nv_bfloat16 l = __float2bfloat16(v - __bfloat162float(h));
    g_wh[n * FDIM + k] = h;
    g_wl[n * FDIM + k] = l;
}

// ---------------------------------------------------------------------------
// Kernel 4: xt = x @ W via bf16 mma.sync, 3-term split.
// A fragments loaded DIRECTLY from global into registers; B (hi+lo, full
// K=256) resident in smem. No barriers in the k-loop. fp16 epilogue.
// ---------------------------------------------------------------------------
#define BSTR  264                // B smem row stride in halves (256 + 8 pad)
#define SB_H  0                  // 64 * 264 * 2 = 33792 bytes per plane
#define SB_L  33792
#define S_TOT 67584

extern __shared__ char dsm[];

__device__ __forceinline__ uint32_t smem_u32(const void* p) {
    uint32_t a;
    asm("{ .reg .u64 t; cvta.to.shared.u64 t, %1; cvt.u32.u64 %0, t; }"
        : "=r"(a) : "l"(p));
    return a;
}
__device__ __forceinline__ void ldsm_x2(uint32_t* r, uint32_t addr) {
    asm volatile("ldmatrix.sync.aligned.m8n8.x2.shared.b16 {%0,%1}, [%2];"
                 : "=r"(r[0]), "=r"(r[1]) : "r"(addr));
}
__device__ __forceinline__ void mma_bf16(float* c, const uint32_t* a,
                                         const uint32_t* b) {
    asm volatile(
        "mma.sync.aligned.m16n8k16.row.col.f32.bf16.bf16.f32 "
        "{%0,%1,%2,%3}, {%4,%5,%6,%7}, {%8,%9}, {%0,%1,%2,%3};"
        : "+f"(c[0]), "+f"(c[1]), "+f"(c[2]), "+f"(c[3])
        : "r"(a[0]), "r"(a[1]), "r"(a[2]), "r"(a[3]), "r"(b[0]), "r"(b[1]));
}
__device__ __forceinline__ uint32_t packbf2(float a, float b) {
    __nv_bfloat162 p = __floats2bfloat162_rn(a, b);
    return *(uint32_t*)&p;
}
__device__ __forceinline__ void cvt_hilo(float2 v, uint32_t& h, uint32_t& l) {
    __nv_bfloat16 h0 = __float2bfloat16(v.x);
    __nv_bfloat16 h1 = __float2bfloat16(v.y);
    h = (uint32_t)__bfloat16_as_ushort(h0) |
        ((uint32_t)__bfloat16_as_ushort(h1) << 16);
    l = packbf2(v.x - __bfloat162float(h0), v.y - __bfloat162float(h1));
}

__global__ void __launch_bounds__(256, 2)
k_gemm_tc(const float* __restrict__ x) {
    const int tid  = threadIdx.x;
    const int lane = tid & 31;
    const int w    = tid >> 5;
    const int wm   = w >> 1;          // 0..3 (32-row block)
    const int wn   = w & 1;           // 0..1 (32-col block)
    const int n0   = blockIdx.x * 64;
    const int m0   = blockIdx.y * 128;
    const uint32_t sb = smem_u32(dsm);

    // ---- preload B (hi + lo, 64 n x 256 k) into smem ----
    #pragma unroll
    for (int q = 0; q < 8; q++) {
        int idx = q * 256 + tid;
        int n = idx >> 5;
        int u = idx & 31;
        *(uint4*)(dsm + SB_H + n * (BSTR * 2) + u * 16) =
            *(const uint4*)&g_wh[(size_t)(n0 + n) * FDIM + u * 8];
        *(uint4*)(dsm + SB_L + n * (BSTR * 2) + u * 16) =
            *(const uint4*)&g_wl[(size_t)(n0 + n) * FDIM + u * 8];
    }
    __syncthreads();

    const float* ap = x + (size_t)(m0 + wm * 32 + (lane >> 2)) * FDIM +
                      ((lane & 3) << 1);
    const uint32_t brow = (uint32_t)(wn * 32 + (lane & 7)) * (BSTR * 2) +
                          (uint32_t)(((lane >> 3) & 1) * 8) * 2;

    float acc[2][4][4];
    #pragma unroll
    for (int i = 0; i < 2; i++)
        #pragma unroll
        for (int j = 0; j < 4; j++)
            #pragma unroll
            for (int r = 0; r < 4; r++) acc[i][j][r] = 0.f;

    float2 pv[2][4];
    #pragma unroll
    for (int i = 0; i < 2; i++) {
        const float* p = ap + i * 16 * FDIM;
        pv[i][0] = *(const float2*)(p);
        pv[i][1] = *(const float2*)(p + 8 * FDIM);
        pv[i][2] = *(const float2*)(p + 8);
        pv[i][3] = *(const float2*)(p + 8 * FDIM + 8);
    }

    #pragma unroll
    for (int kk = 0; kk < 16; kk++) {
        float2 nv[2][4];
        if (kk + 1 < 16) {
            const int kn = (kk + 1) * 16;
            #pragma unroll
            for (int i = 0; i < 2; i++) {
                const float* p = ap + i * 16 * FDIM + kn;
                nv[i][0] = *(const float2*)(p);
                nv[i][1] = *(const float2*)(p + 8 * FDIM);
                nv[i][2] = *(const float2*)(p + 8);
                nv[i][3] = *(const float2*)(p + 8 * FDIM + 8);
            }
        }

        uint32_t aH[2][4], aL[2][4];
        #pragma unroll
        for (int i = 0; i < 2; i++)
            #pragma unroll
            for (int q = 0; q < 4; q++)
                cvt_hilo(pv[i][q], aH[i][q], aL[i][q]);

        const uint32_t kb = (uint32_t)(kk * 16) * 2;
        uint32_t bH[4][2], bL[4][2];
        #pragma unroll
        for (int j = 0; j < 4; j++)
            ldsm_x2(bH[j], sb + SB_H + brow + kb + j * 8 * (BSTR * 2));
        #pragma unroll
        for (int j = 0; j < 4; j++)
            ldsm_x2(bL[j], sb + SB_L + brow + kb + j * 8 * (BSTR * 2));

        #pragma unroll
        for (int i = 0; i < 2; i++)
            #pragma unroll
            for (int j = 0; j < 4; j++) mma_bf16(acc[i][j], aH[i], bH[j]);
        #pragma unroll
        for (int i = 0; i < 2; i++)
            #pragma unroll
            for (int j = 0; j < 4; j++) mma_bf16(acc[i][j], aH[i], bL[j]);
        #pragma unroll
        for (int i = 0; i < 2; i++)
            #pragma unroll
            for (int j = 0; j < 4; j++) mma_bf16(acc[i][j], aL[i], bH[j]);

        #pragma unroll
        for (int i = 0; i < 2; i++)
            #pragma unroll
            for (int q = 0; q < 4; q++) pv[i][q] = nv[i][q];
    }

    // ---- epilogue: D fragment -> g_xth (fp16) ----
    #pragma unroll
    for (int i = 0; i < 2; i++) {
        #pragma unroll
        for (int j = 0; j < 4; j++) {
            int m = m0 + wm * 32 + i * 16 + (lane >> 2);
            int n = n0 + wn * 32 + j * 8 + (lane & 3) * 2;
            *(__half2*)&g_xth[(size_t)m * FDIM + n] =
                __float22half2_rn(make_float2(acc[i][j][0], acc[i][j][1]));
            *(__half2*)&g_xth[(size_t)(m + 8) * FDIM + n] =
                __float22half2_rn(make_float2(acc[i][j][2], acc[i][j][3]));
        }
    }
}

// ---------------------------------------------------------------------------
// Kernel 5: sparse aggregation over fp16 xt.
// One src per block (balanced). 256 threads = 128 half2 feature lanes x
// 2 neighbor-halves of the SAME row (counts differ by <=1). fp32 accumulate;
// smem merge; half traffic vs fp32.
// ---------------------------------------------------------------------------
__global__ void __launch_bounds__(256)
k_agg(const float* __restrict__ bias, float* __restrict__ out) {
    const int src  = blockIdx.x;
    const int tid  = threadIdx.x;
    const int half = tid >> 7;           // neighbor-half
    const int t    = tid & 127;          // feature-pair lane
    const int f    = t << 1;

    __shared__ int    snb[MAXD];
    __shared__ float2 red[128][BB];      // 8 KB merge buffer

    int deg = g_deg[src];
    if (deg > MAXD) deg = MAXD;
    if (tid < deg) snb[tid] = g_nbr[src * MAXD + tid];
    __syncthreads();

    const int i0 = half ? (deg >> 1) : 0;
    const int i1 = half ? deg : (deg >> 1);

    float2 acc[BB];
    #pragma unroll
    for (int b = 0; b < BB; b++) acc[b] = make_float2(0.f, 0.f);

    const size_t batch_stride = (size_t)NN * FDIM;

    int i = i0;
    for (; i + 2 <= i1; i += 2) {
        const __half* p0 = &g_xth[(size_t)snb[i]     * FDIM + f];
        const __half* p1 = &g_xth[(size_t)snb[i + 1] * FDIM + f];
        __half2 v0[BB], v1[BB];
        #pragma unroll
        for (int b = 0; b < BB; b++) v0[b] = *(const __half2*)(p0 + b * batch_stride);
        #pragma unroll
        for (int b = 0; b < BB; b++) v1[b] = *(const __half2*)(p1 + b * batch_stride);
        #pragma unroll
        for (int b = 0; b < BB; b++) {
            float2 a = __half22float2(v0[b]);
            float2 c = __half22float2(v1[b]);
            acc[b].x += a.x + c.x;
            acc[b].y += a.y + c.y;
        }
    }
    if (i < i1) {
        const __half* p0 = &g_xth[(size_t)snb[i] * FDIM + f];
        #pragma unroll
        for (int b = 0; b < BB; b++) {
            float2 a = __half22float2(*(const __half2*)(p0 + b * batch_stride));
            acc[b].x += a.x;
            acc[b].y += a.y;
        }
    }

    // merge the two neighbor-halves
    if (half) {
        #pragma unroll
        for (int b = 0; b < BB; b++) red[t][b] = acc[b];
    }
    __syncthreads();

    if (!half) {
        const float inv = 1.0f / ((float)deg + 1e-6f);
        const float2 bf = *(const float2*)&bias[f];
        #pragma unroll
        for (int b = 0; b < BB; b++) {
            float2 o = red[t][b];
            o.x = (acc[b].x + o.x) * inv + bf.x;
            o.y = (acc[b].y + o.y) * inv + bf.y;
            *(float2*)&out[((size_t)b * NN + src) * FDIM + f] = o;
        }
    }
}

// ---------------------------------------------------------------------------
extern "C" void kernel_launch(void* const* d_in, const int* in_sizes, int n_in,
                              void* d_out, int out_size) {
    const float* x    = (const float*)d_in[0];   // (8, 4096, 256) f32
    const int*   ei   = (const int*)  d_in[1];   // (2, 131072) i32
    const float* w    = (const float*)d_in[2];   // (256, 256) f32
    const float* bias = (const float*)d_in[3];   // (256,) f32
    float* out = (float*)d_out;

    const int E = in_sizes[1] / 2;

    cudaFuncSetAttribute(k_gemm_tc, cudaFuncAttributeMaxDynamicSharedMemorySize,
                         S_TOT);

    k_zero<<<(NN * WPR + 255) / 256, 256>>>();
    k_edges<<<(E + 255) / 256, 256>>>(ei, E);
    k_wprep<<<(FDIM * FDIM + 255) / 256, 256>>>(w);
    k_gemm_tc<<<dim3(4, MTOT / 128), 256, S_TOT>>>(x);
    k_agg<<<NN, 256>>>(bias, out);
}